// round 5
// baseline (speedup 1.0000x reference)
#include <cuda_runtime.h>

#define THR 0.5f
#define MIN_JUMP_ENERGY 0.5f
#define MIN_VELOCITY_THRESHOLD 0.1f
#define MIN_WALL_JUMP_SPEED 1.0f

static constexpr int B = 32;
static constexpr int E = 100000;               // 32 | E -> tiles never cross batch
static constexpr int NTILES = (B * E) / 32;    // 100000 tiles of 32 rows
static constexpr int NBLOCKS = 148 * 8;        // single wave on 148 SMs

__device__ __forceinline__ float4 ldcs4(const float4* p) {
    return __ldcs(p);
}

__global__ __launch_bounds__(256) void edge_mask_kernel(
    const float4* __restrict__ feat,     // [B, E, 16] as float4[B*E*4]
    const float*  __restrict__ phys,     // [B, 18]
    const float*  __restrict__ base,     // [B, E]
    float*        __restrict__ out)      // [B, E]
{
    __shared__ float4 sh[8][128];        // 2 KB per warp

    const int warp = threadIdx.x >> 5;
    const int lane = threadIdx.x & 31;
    float4* s = sh[warp];

    for (int tile = blockIdx.x * 8 + warp; tile < NTILES; tile += NBLOCKS * 8) {
        const int  flatRowBase = tile * 32;
        const int  b = flatRowBase / E;          // uniform per warp
        const size_t rowBase = (size_t)flatRowBase;

        // Per-batch physics scalars (uniform; hot in L2/L1)
        const float* p = phys + b * 18;
        const float vel  = p[2];
        const float wall = p[5];
        const float ke   = p[9];
        const float cj   = p[16];
        const float cwj  = p[17];

        // Front-batched streaming loads
        const float   bval = __ldcs(base + rowBase + lane);
        const float4* fB   = feat + rowBase * 4;
        float4 v0 = ldcs4(fB +   0 + lane);
        float4 v1 = ldcs4(fB +  32 + lane);
        float4 v2 = ldcs4(fB +  64 + lane);
        float4 v3 = ldcs4(fB +  96 + lane);

        // Swizzled store: flat chunk index i; sw(i) = i ^ ((i>>2)&7)
        {
            const int i0 = 0  * 32 + lane;
            const int i1 = 1  * 32 + lane;
            const int i2 = 2  * 32 + lane;
            const int i3 = 3  * 32 + lane;
            s[i0 ^ ((i0 >> 2) & 7)] = v0;
            s[i1 ^ ((i1 >> 2) & 7)] = v1;
            s[i2 ^ ((i2 >> 2) & 7)] = v2;
            s[i3 ^ ((i3 >> 2) & 7)] = v3;
        }
        __syncwarp();

        // Swizzled read: this thread's row = lane
        const int j0 = lane * 4 + 0;
        const int j1 = lane * 4 + 1;
        const int j2 = lane * 4 + 2;
        const int j3 = lane * 4 + 3;
        const float4 c0 = s[j0 ^ ((j0 >> 2) & 7)];
        const float4 c1 = s[j1 ^ ((j1 >> 2) & 7)];
        const float4 c2 = s[j2 ^ ((j2 >> 2) & 7)];
        const float4 c3 = s[j3 ^ ((j3 >> 2) & 7)];
        __syncwarp();   // tile buffer reused next iteration

        // argmax over cols 0..5, first-max-wins (strict >)
        int   et = 0;
        float mx = c0.x;
        if (c0.y > mx) { mx = c0.y; et = 1; }
        if (c0.z > mx) { mx = c0.z; et = 2; }
        if (c0.w > mx) { mx = c0.w; et = 3; }
        if (c1.x > mx) { mx = c1.x; et = 4; }
        if (c1.y > mx) { mx = c1.y; et = 5; }

        const float energy_cost           = c2.z;  // col 10
        const float min_velocity          = c3.x;  // col 12
        const float max_velocity          = c3.y;  // col 13
        const float requires_jump         = c3.z;  // col 14
        const float requires_wall_contact = c3.w;  // col 15

        // jnp.select: first-true-wins priority chain
        const bool cc1 = (et == 1) && (cj < THR);
        const bool cc2 = (et == 3);
        const bool d2  = (wall < THR) || (vel < MIN_VELOCITY_THRESHOLD);
        const bool cc3 = (requires_jump > THR);
        const bool d3  = (cj < THR) || (vel < min_velocity);
        const bool cc4 = (requires_wall_contact > THR);
        const bool d4  = (wall < THR) ||
                         ((cwj < THR) && (vel < MIN_WALL_JUMP_SPEED));
        const bool cc5 = (et == 1);
        const bool d5  = (ke < energy_cost * MIN_JUMP_ENERGY);

        bool dis;
        if      (cc1) dis = true;
        else if (cc2) dis = d2;
        else if (cc3) dis = d3;
        else if (cc4) dis = d4;
        else if (cc5) dis = d5;
        else          dis = false;

        const bool over  = (max_velocity > 0.0f) && (vel > max_velocity);
        const bool under = (!over) && (vel < min_velocity);
        dis = dis || over || under;

        __stcs(out + rowBase + lane, dis ? 0.0f : bval);
    }
}

extern "C" void kernel_launch(void* const* d_in, const int* in_sizes, int n_in,
                              void* d_out, int out_size)
{
    const float4* feat = (const float4*)d_in[0];
    const float*  phys = (const float*) d_in[1];
    const float*  base = (const float*) d_in[2];
    float*        out  = (float*)d_out;

    edge_mask_kernel<<<NBLOCKS, 256>>>(feat, phys, base, out);
}

// round 6
// speedup vs baseline: 1.1038x; 1.1038x over previous
#include <cuda_runtime.h>

#define THR 0.5f
#define MIN_JUMP_ENERGY 0.5f
#define MIN_VELOCITY_THRESHOLD 0.1f
#define MIN_WALL_JUMP_SPEED 1.0f

static constexpr int B = 32;
static constexpr int E = 100000;   // divisible by 32: warps are all-in or all-out

__global__ __launch_bounds__(256) void edge_mask_kernel(
    const float4* __restrict__ feat,     // [B, E, 16] as float4[B*E*4]
    const float*  __restrict__ phys,     // [B, 18]
    const float*  __restrict__ base,     // [B, E]
    float*        __restrict__ out)      // [B, E]
{
    __shared__ float4 sh[8][128];        // 2 KB per warp, 16 KB per block

    const int b    = blockIdx.y;
    const int warp = threadIdx.x >> 5;
    const int lane = threadIdx.x & 31;
    const int warpRowBase = blockIdx.x * 256 + warp * 32;
    if (warpRowBase >= E) return;        // whole-warp uniform (E % 32 == 0)

    // Per-batch physics scalars (uniform, cached)
    const float* p = phys + b * 18;
    const float vel  = p[2];
    const float wall = p[5];
    const float ke   = p[9];
    const float cj   = p[16];
    const float cwj  = p[17];

    const size_t  bOff = (size_t)b * E;
    const float4* fB   = feat + (bOff + (size_t)warpRowBase) * 4;

    // Front-batched streaming loads: 1 coalesced base + 4 coalesced 512B feature loads
    const float bval = __ldcs(base + bOff + warpRowBase + lane);

    float4 v0 = __ldcs(fB +   0 + lane);
    float4 v1 = __ldcs(fB +  32 + lane);
    float4 v2 = __ldcs(fB +  64 + lane);
    float4 v3 = __ldcs(fB +  96 + lane);

    // Swizzled store: flat chunk index i = row*4 + chunk; sw(i) = i ^ ((i>>2)&7)
    float4* s = sh[warp];
    {
        const int i0 = 0 * 32 + lane;
        const int i1 = 1 * 32 + lane;
        const int i2 = 2 * 32 + lane;
        const int i3 = 3 * 32 + lane;
        s[i0 ^ ((i0 >> 2) & 7)] = v0;
        s[i1 ^ ((i1 >> 2) & 7)] = v1;
        s[i2 ^ ((i2 >> 2) & 7)] = v2;
        s[i3 ^ ((i3 >> 2) & 7)] = v3;
    }
    __syncwarp();

    // Swizzled read: this thread's row = lane; chunks 0..3
    const int j0 = lane * 4 + 0;
    const int j1 = lane * 4 + 1;
    const int j2 = lane * 4 + 2;
    const int j3 = lane * 4 + 3;
    const float4 c0 = s[j0 ^ ((j0 >> 2) & 7)];
    const float4 c1 = s[j1 ^ ((j1 >> 2) & 7)];
    const float4 c2 = s[j2 ^ ((j2 >> 2) & 7)];
    const float4 c3 = s[j3 ^ ((j3 >> 2) & 7)];

    // argmax over cols 0..5, first-max-wins (strict >)
    int   et = 0;
    float mx = c0.x;
    if (c0.y > mx) { mx = c0.y; et = 1; }
    if (c0.z > mx) { mx = c0.z; et = 2; }
    if (c0.w > mx) { mx = c0.w; et = 3; }
    if (c1.x > mx) { mx = c1.x; et = 4; }
    if (c1.y > mx) { mx = c1.y; et = 5; }

    const float energy_cost           = c2.z;  // col 10
    const float min_velocity          = c3.x;  // col 12
    const float max_velocity          = c3.y;  // col 13
    const float requires_jump         = c3.z;  // col 14
    const float requires_wall_contact = c3.w;  // col 15

    // jnp.select: first-true-wins priority chain
    const bool cc1 = (et == 1) && (cj < THR);
    const bool cc2 = (et == 3);
    const bool d2  = (wall < THR) || (vel < MIN_VELOCITY_THRESHOLD);
    const bool cc3 = (requires_jump > THR);
    const bool d3  = (cj < THR) || (vel < min_velocity);
    const bool cc4 = (requires_wall_contact > THR);
    const bool d4  = (wall < THR) ||
                     ((cwj < THR) && (vel < MIN_WALL_JUMP_SPEED));
    const bool cc5 = (et == 1);
    const bool d5  = (ke < energy_cost * MIN_JUMP_ENERGY);

    bool dis;
    if      (cc1) dis = true;
    else if (cc2) dis = d2;
    else if (cc3) dis = d3;
    else if (cc4) dis = d4;
    else if (cc5) dis = d5;
    else          dis = false;

    const bool over  = (max_velocity > 0.0f) && (vel > max_velocity);
    const bool under = (!over) && (vel < min_velocity);
    dis = dis || over || under;

    __stcs(out + bOff + warpRowBase + lane, dis ? 0.0f : bval);
}

extern "C" void kernel_launch(void* const* d_in, const int* in_sizes, int n_in,
                              void* d_out, int out_size)
{
    const float4* feat = (const float4*)d_in[0];
    const float*  phys = (const float*) d_in[1];
    const float*  base = (const float*) d_in[2];
    float*        out  = (float*)d_out;

    dim3 block(256);
    dim3 grid((E + 255) / 256, B);
    edge_mask_kernel<<<grid, block>>>(feat, phys, base, out);
}